// round 1
// baseline (speedup 1.0000x reference)
#include <cuda_runtime.h>
#include <math.h>

#define NPTS   65536
#define BATCH  4
#define HGT    64
#define WID    64
#define DM     128
#define MLPW   256
#define NFREQ  10
#define ENCD   (2 + 4*NFREQ)      // 42
#define IN0    (ENCD + DM)        // 170
#define MTILE  64
#define SSTR   260                // smem row stride in floats (>=256, 16B-aligned rows)

// smem layout (floats): h[MTILE*SSTR] | gamma1[256] | beta[256] | wout[768]
#define SH_H      0
#define SH_G      (MTILE*SSTR)
#define SH_B      (SH_G + MLPW)
#define SH_WO     (SH_B + MLPW)
#define SMEM_FLOATS (SH_WO + 768)
#define SMEM_BYTES  (SMEM_FLOATS * 4)

__device__ float g_gamma1[BATCH * MLPW];
__device__ float g_beta[BATCH * MLPW];

// ---------------- packed f32x2 helpers ----------------
__device__ __forceinline__ unsigned long long fma2(unsigned long long a,
                                                   unsigned long long b,
                                                   unsigned long long c) {
    unsigned long long d;
    asm("fma.rn.f32x2 %0, %1, %2, %3;" : "=l"(d) : "l"(a), "l"(b), "l"(c));
    return d;
}
__device__ __forceinline__ unsigned long long pack2(float x) {
    unsigned long long d;
    unsigned int r = __float_as_uint(x);
    asm("mov.b64 %0, {%1, %1};" : "=l"(d) : "r"(r));
    return d;
}
__device__ __forceinline__ float2 unpack2(unsigned long long v) {
    unsigned int lo, hi;
    asm("mov.b64 {%0, %1}, %2;" : "=r"(lo), "=r"(hi) : "l"(v));
    return make_float2(__uint_as_float(lo), __uint_as_float(hi));
}

__device__ __forceinline__ float gelu_tanh(float x) {
    // jax.nn.gelu default (approximate=True): 0.5*x*(1+tanh(sqrt(2/pi)*(x+0.044715*x^3)))
    float u = 0.7978845608028654f * fmaf(0.044715f * x, x * x, x);
    return 0.5f * x * (1.0f + tanhf(u));
}

// ---------------- FiLM precompute: ctx @ w_film + b_film ----------------
__global__ void film_kernel(const float* __restrict__ ctx,
                            const float* __restrict__ wf,
                            const float* __restrict__ bf) {
    int b = blockIdx.x;
    int j = threadIdx.x;                 // 0..511
    float acc = bf[j];
    const float* c = ctx + b * DM;
#pragma unroll 4
    for (int k = 0; k < DM; k++)
        acc = fmaf(__ldg(&c[k]), __ldg(&wf[k * 2 * MLPW + j]), acc);
    if (j < MLPW) g_gamma1[b * MLPW + j] = acc + 1.0f;
    else          g_beta[b * MLPW + (j - MLPW)] = acc;
}

// ---------------- one MLP layer: h(KDIM) @ W(KDIM x 256) + b, FiLM, gelu ----------------
template <int KDIM>
__device__ __forceinline__ void mlp_layer(float* shh, const float* shg, const float* shb,
                                          const float* __restrict__ w,
                                          const float* __restrict__ bias,
                                          int tx, int ty) {
    unsigned long long acc[4][8];
#pragma unroll
    for (int jj = 0; jj < 4; jj++) {
        ulonglong2 bv = __ldg((const ulonglong2*)(bias + tx * 4 + 64 * jj));
#pragma unroll
        for (int i = 0; i < 4; i++) { acc[i][2*jj] = bv.x; acc[i][2*jj+1] = bv.y; }
    }
    const float* h0 = shh + (ty * 4) * SSTR;
    const float* wr = w + tx * 4;
#pragma unroll 2
    for (int k = 0; k < KDIM; k++) {
        unsigned long long a0 = pack2(h0[k]);
        unsigned long long a1 = pack2(h0[SSTR + k]);
        unsigned long long a2 = pack2(h0[2 * SSTR + k]);
        unsigned long long a3 = pack2(h0[3 * SSTR + k]);
        const float* wk = wr + k * 256;
#pragma unroll
        for (int jj = 0; jj < 4; jj++) {
            ulonglong2 wv = __ldg((const ulonglong2*)(wk + 64 * jj));
            acc[0][2*jj]   = fma2(a0, wv.x, acc[0][2*jj]);
            acc[1][2*jj]   = fma2(a1, wv.x, acc[1][2*jj]);
            acc[2][2*jj]   = fma2(a2, wv.x, acc[2][2*jj]);
            acc[3][2*jj]   = fma2(a3, wv.x, acc[3][2*jj]);
            acc[0][2*jj+1] = fma2(a0, wv.y, acc[0][2*jj+1]);
            acc[1][2*jj+1] = fma2(a1, wv.y, acc[1][2*jj+1]);
            acc[2][2*jj+1] = fma2(a2, wv.y, acc[2][2*jj+1]);
            acc[3][2*jj+1] = fma2(a3, wv.y, acc[3][2*jj+1]);
        }
    }
    __syncthreads();   // everyone done reading shh
#pragma unroll
    for (int jj = 0; jj < 4; jj++) {
        int nb = tx * 4 + 64 * jj;
        float g0 = shg[nb], g1 = shg[nb+1], g2 = shg[nb+2], g3 = shg[nb+3];
        float e0 = shb[nb], e1 = shb[nb+1], e2 = shb[nb+2], e3 = shb[nb+3];
#pragma unroll
        for (int i = 0; i < 4; i++) {
            float2 v0 = unpack2(acc[i][2*jj]);
            float2 v1 = unpack2(acc[i][2*jj+1]);
            float z0 = gelu_tanh(fmaf(v0.x, g0, e0));
            float z1 = gelu_tanh(fmaf(v0.y, g1, e1));
            float z2 = gelu_tanh(fmaf(v1.x, g2, e2));
            float z3 = gelu_tanh(fmaf(v1.y, g3, e3));
            *(float4*)(shh + (ty * 4 + i) * SSTR + nb) = make_float4(z0, z1, z2, z3);
        }
    }
    __syncthreads();
}

// ---------------- main decoder kernel ----------------
__global__ void __launch_bounds__(256, 2)
decoder_kernel(const float* __restrict__ fgrid,
               const float* __restrict__ coords,
               const float* __restrict__ w0, const float* __restrict__ b0,
               const float* __restrict__ w1, const float* __restrict__ b1,
               const float* __restrict__ w2, const float* __restrict__ b2,
               const float* __restrict__ w3, const float* __restrict__ b3,
               const float* __restrict__ wo, const float* __restrict__ bo,
               float* __restrict__ out) {
    extern __shared__ float sh[];
    float* shh = sh + SH_H;
    float* shg = sh + SH_G;
    float* shb = sh + SH_B;
    float* shwo = sh + SH_WO;

    const int b   = blockIdx.y;
    const int n0  = blockIdx.x * MTILE;
    const int tid = threadIdx.x;
    const int tx  = tid & 15;
    const int ty  = tid >> 4;

    // stage FiLM params + w_out into smem
    if (tid < MLPW) {
        shg[tid] = g_gamma1[b * MLPW + tid];
        shb[tid] = g_beta[b * MLPW + tid];
    }
#pragma unroll
    for (int i = tid; i < 768; i += 256) shwo[i] = __ldg(&wo[i]);

    // ---------- Phase A: build h0 = [enc(42) | bilinear sample(128)] ----------
    {
        const int p   = tid >> 2;       // point within tile (4 threads/point)
        const int sub = tid & 3;
        const int n   = n0 + p;
        float cy = __ldg(&coords[2 * n]);
        float cx = __ldg(&coords[2 * n + 1]);
        float py = fminf(fmaxf((cy + 1.0f) * 31.5f, 0.0f), 63.0f);
        float px = fminf(fmaxf((cx + 1.0f) * 31.5f, 0.0f), 63.0f);
        int y0i = min((int)py, 62);
        int x0i = min((int)px, 62);
        float fy = py - (float)y0i;
        float fx = px - (float)x0i;
        float w00 = (1.0f - fy) * (1.0f - fx);
        float w01 = (1.0f - fy) * fx;
        float w10 = fy * (1.0f - fx);
        float w11 = fy * fx;
        const float* gbase = fgrid + (((size_t)b * HGT + y0i) * WID + x0i) * DM;
        const float4* q00 = (const float4*)gbase;
        const float4* q01 = (const float4*)(gbase + DM);
        const float4* q10 = (const float4*)(gbase + WID * DM);
        const float4* q11 = (const float4*)(gbase + WID * DM + DM);
        float* dst = shh + p * SSTR + ENCD + sub * 32;
#pragma unroll
        for (int q = 0; q < 8; q++) {
            int idx = sub * 8 + q;
            float4 aa = __ldg(&q00[idx]);
            float4 bb = __ldg(&q01[idx]);
            float4 cc = __ldg(&q10[idx]);
            float4 dd = __ldg(&q11[idx]);
            dst[4*q+0] = w00*aa.x + w01*bb.x + w10*cc.x + w11*dd.x;
            dst[4*q+1] = w00*aa.y + w01*bb.y + w10*cc.y + w11*dd.y;
            dst[4*q+2] = w00*aa.z + w01*bb.z + w10*cc.z + w11*dd.z;
            dst[4*q+3] = w00*aa.w + w01*bb.w + w10*cc.w + w11*dd.w;
        }
        if (sub == 0) {
            float* e = shh + p * SSTR;
            e[0] = cy; e[1] = cx;
            float f = 3.14159265358979323846f;
#pragma unroll
            for (int i = 0; i < NFREQ; i++) {
                float s0, c0, s1, c1;
                sincosf(cy * f, &s0, &c0);
                sincosf(cx * f, &s1, &c1);
                e[2 + 4*i + 0] = s0;   // sin over coord dims
                e[2 + 4*i + 1] = s1;
                e[2 + 4*i + 2] = c0;   // cos over coord dims
                e[2 + 4*i + 3] = c1;
                f *= 2.0f;
            }
        }
    }
    __syncthreads();

    // ---------- 4 FiLM-GELU layers ----------
    mlp_layer<IN0 >(shh, shg, shb, w0, b0, tx, ty);
    mlp_layer<MLPW>(shh, shg, shb, w1, b1, tx, ty);
    mlp_layer<MLPW>(shh, shg, shb, w2, b2, tx, ty);
    mlp_layer<MLPW>(shh, shg, shb, w3, b3, tx, ty);

    // ---------- output head: 256 -> 3, tanh ----------
    if (tid < MTILE * 3) {
        int pp = tid / 3;
        int j  = tid - pp * 3;
        const float* hr = shh + pp * SSTR;
        float acc = __ldg(&bo[j]);
#pragma unroll 8
        for (int k = 0; k < 256; k++)
            acc = fmaf(hr[k], shwo[k * 3 + j], acc);
        out[((size_t)b * NPTS + n0 + pp) * 3 + j] = tanhf(acc);
    }
}

extern "C" void kernel_launch(void* const* d_in, const int* in_sizes, int n_in,
                              void* d_out, int out_size) {
    const float* fgrid  = (const float*)d_in[0];
    const float* ctx    = (const float*)d_in[1];
    const float* coords = (const float*)d_in[2];
    const float* w0 = (const float*)d_in[3];
    const float* b0 = (const float*)d_in[4];
    const float* w1 = (const float*)d_in[5];
    const float* b1 = (const float*)d_in[6];
    const float* w2 = (const float*)d_in[7];
    const float* b2 = (const float*)d_in[8];
    const float* w3 = (const float*)d_in[9];
    const float* b3 = (const float*)d_in[10];
    const float* wf = (const float*)d_in[11];
    const float* bf = (const float*)d_in[12];
    const float* wo = (const float*)d_in[13];
    const float* bo = (const float*)d_in[14];
    float* out = (float*)d_out;

    cudaFuncSetAttribute(decoder_kernel,
                         cudaFuncAttributeMaxDynamicSharedMemorySize, SMEM_BYTES);

    film_kernel<<<BATCH, 2 * MLPW>>>(ctx, wf, bf);
    dim3 grid(NPTS / MTILE, BATCH);
    decoder_kernel<<<grid, 256, SMEM_BYTES>>>(fgrid, coords,
                                              w0, b0, w1, b1, w2, b2, w3, b3,
                                              wo, bo, out);
}

// round 2
// speedup vs baseline: 1.0021x; 1.0021x over previous
#include <cuda_runtime.h>
#include <math.h>

#define NPTS   65536
#define BATCH  4
#define HGT    64
#define WID    64
#define DM     128
#define MLPW   256
#define NFREQ  10
#define ENCD   (2 + 4*NFREQ)      // 42
#define IN0    (ENCD + DM)        // 170
#define MTILE  64
#define SSTR   260                // smem row stride in floats (>=256, 16B-aligned rows)

// smem layout (floats): h[MTILE*SSTR] | gamma1[256] | beta[256] | wout[768]
#define SH_H      0
#define SH_G      (MTILE*SSTR)
#define SH_B      (SH_G + MLPW)
#define SH_WO     (SH_B + MLPW)
#define SMEM_FLOATS (SH_WO + 768)
#define SMEM_BYTES  (SMEM_FLOATS * 4)

__device__ float g_gamma1[BATCH * MLPW];
__device__ float g_beta[BATCH * MLPW];

// ---------------- packed f32x2 helpers ----------------
__device__ __forceinline__ unsigned long long fma2(unsigned long long a,
                                                   unsigned long long b,
                                                   unsigned long long c) {
    unsigned long long d;
    asm("fma.rn.f32x2 %0, %1, %2, %3;" : "=l"(d) : "l"(a), "l"(b), "l"(c));
    return d;
}
__device__ __forceinline__ unsigned long long pack2(float x) {
    unsigned long long d;
    unsigned int r = __float_as_uint(x);
    asm("mov.b64 %0, {%1, %1};" : "=l"(d) : "r"(r));
    return d;
}
__device__ __forceinline__ float2 unpack2(unsigned long long v) {
    unsigned int lo, hi;
    asm("mov.b64 {%0, %1}, %2;" : "=r"(lo), "=r"(hi) : "l"(v));
    return make_float2(__uint_as_float(lo), __uint_as_float(hi));
}

__device__ __forceinline__ float gelu_tanh(float x) {
    // jax.nn.gelu default (approximate=True): 0.5*x*(1+tanh(sqrt(2/pi)*(x+0.044715*x^3)))
    float u = 0.7978845608028654f * fmaf(0.044715f * x, x * x, x);
    return 0.5f * x * (1.0f + tanhf(u));
}

// ---------------- FiLM precompute: ctx @ w_film + b_film ----------------
__global__ void film_kernel(const float* __restrict__ ctx,
                            const float* __restrict__ wf,
                            const float* __restrict__ bf) {
    int b = blockIdx.x;
    int j = threadIdx.x;                 // 0..511
    float acc = bf[j];
    const float* c = ctx + b * DM;
#pragma unroll 4
    for (int k = 0; k < DM; k++)
        acc = fmaf(__ldg(&c[k]), __ldg(&wf[k * 2 * MLPW + j]), acc);
    if (j < MLPW) g_gamma1[b * MLPW + j] = acc + 1.0f;
    else          g_beta[b * MLPW + (j - MLPW)] = acc;
}

// ---------------- one MLP layer: h(KDIM) @ W(KDIM x 256) + b, FiLM, gelu ----------------
template <int KDIM>
__device__ __forceinline__ void mlp_layer(float* shh, const float* shg, const float* shb,
                                          const float* __restrict__ w,
                                          const float* __restrict__ bias,
                                          int tx, int ty) {
    unsigned long long acc[4][8];
#pragma unroll
    for (int jj = 0; jj < 4; jj++) {
        ulonglong2 bv = __ldg((const ulonglong2*)(bias + tx * 4 + 64 * jj));
#pragma unroll
        for (int i = 0; i < 4; i++) { acc[i][2*jj] = bv.x; acc[i][2*jj+1] = bv.y; }
    }
    const float* h0 = shh + (ty * 4) * SSTR;
    const float* wr = w + tx * 4;
#pragma unroll 2
    for (int k = 0; k < KDIM; k++) {
        unsigned long long a0 = pack2(h0[k]);
        unsigned long long a1 = pack2(h0[SSTR + k]);
        unsigned long long a2 = pack2(h0[2 * SSTR + k]);
        unsigned long long a3 = pack2(h0[3 * SSTR + k]);
        const float* wk = wr + k * 256;
#pragma unroll
        for (int jj = 0; jj < 4; jj++) {
            ulonglong2 wv = __ldg((const ulonglong2*)(wk + 64 * jj));
            acc[0][2*jj]   = fma2(a0, wv.x, acc[0][2*jj]);
            acc[1][2*jj]   = fma2(a1, wv.x, acc[1][2*jj]);
            acc[2][2*jj]   = fma2(a2, wv.x, acc[2][2*jj]);
            acc[3][2*jj]   = fma2(a3, wv.x, acc[3][2*jj]);
            acc[0][2*jj+1] = fma2(a0, wv.y, acc[0][2*jj+1]);
            acc[1][2*jj+1] = fma2(a1, wv.y, acc[1][2*jj+1]);
            acc[2][2*jj+1] = fma2(a2, wv.y, acc[2][2*jj+1]);
            acc[3][2*jj+1] = fma2(a3, wv.y, acc[3][2*jj+1]);
        }
    }
    __syncthreads();   // everyone done reading shh
#pragma unroll
    for (int jj = 0; jj < 4; jj++) {
        int nb = tx * 4 + 64 * jj;
        float g0 = shg[nb], g1 = shg[nb+1], g2 = shg[nb+2], g3 = shg[nb+3];
        float e0 = shb[nb], e1 = shb[nb+1], e2 = shb[nb+2], e3 = shb[nb+3];
#pragma unroll
        for (int i = 0; i < 4; i++) {
            float2 v0 = unpack2(acc[i][2*jj]);
            float2 v1 = unpack2(acc[i][2*jj+1]);
            float z0 = gelu_tanh(fmaf(v0.x, g0, e0));
            float z1 = gelu_tanh(fmaf(v0.y, g1, e1));
            float z2 = gelu_tanh(fmaf(v1.x, g2, e2));
            float z3 = gelu_tanh(fmaf(v1.y, g3, e3));
            *(float4*)(shh + (ty * 4 + i) * SSTR + nb) = make_float4(z0, z1, z2, z3);
        }
    }
    __syncthreads();
}

// ---------------- main decoder kernel ----------------
__global__ void __launch_bounds__(256, 2)
decoder_kernel(const float* __restrict__ fgrid,
               const float* __restrict__ coords,
               const float* __restrict__ w0, const float* __restrict__ b0,
               const float* __restrict__ w1, const float* __restrict__ b1,
               const float* __restrict__ w2, const float* __restrict__ b2,
               const float* __restrict__ w3, const float* __restrict__ b3,
               const float* __restrict__ wo, const float* __restrict__ bo,
               float* __restrict__ out) {
    extern __shared__ float sh[];
    float* shh = sh + SH_H;
    float* shg = sh + SH_G;
    float* shb = sh + SH_B;
    float* shwo = sh + SH_WO;

    const int b   = blockIdx.y;
    const int n0  = blockIdx.x * MTILE;
    const int tid = threadIdx.x;
    const int tx  = tid & 15;
    const int ty  = tid >> 4;

    // stage FiLM params + w_out into smem
    if (tid < MLPW) {
        shg[tid] = g_gamma1[b * MLPW + tid];
        shb[tid] = g_beta[b * MLPW + tid];
    }
#pragma unroll
    for (int i = tid; i < 768; i += 256) shwo[i] = __ldg(&wo[i]);

    // ---------- Phase A: build h0 = [enc(42) | bilinear sample(128)] ----------
    {
        const int p   = tid >> 2;       // point within tile (4 threads/point)
        const int sub = tid & 3;
        const int n   = n0 + p;
        float cy = __ldg(&coords[2 * n]);
        float cx = __ldg(&coords[2 * n + 1]);
        float py = fminf(fmaxf((cy + 1.0f) * 31.5f, 0.0f), 63.0f);
        float px = fminf(fmaxf((cx + 1.0f) * 31.5f, 0.0f), 63.0f);
        int y0i = min((int)py, 62);
        int x0i = min((int)px, 62);
        float fy = py - (float)y0i;
        float fx = px - (float)x0i;
        float w00 = (1.0f - fy) * (1.0f - fx);
        float w01 = (1.0f - fy) * fx;
        float w10 = fy * (1.0f - fx);
        float w11 = fy * fx;
        const float* gbase = fgrid + (((size_t)b * HGT + y0i) * WID + x0i) * DM;
        const float4* q00 = (const float4*)gbase;
        const float4* q01 = (const float4*)(gbase + DM);
        const float4* q10 = (const float4*)(gbase + WID * DM);
        const float4* q11 = (const float4*)(gbase + WID * DM + DM);
        float* dst = shh + p * SSTR + ENCD + sub * 32;
#pragma unroll
        for (int q = 0; q < 8; q++) {
            int idx = sub * 8 + q;
            float4 aa = __ldg(&q00[idx]);
            float4 bb = __ldg(&q01[idx]);
            float4 cc = __ldg(&q10[idx]);
            float4 dd = __ldg(&q11[idx]);
            dst[4*q+0] = w00*aa.x + w01*bb.x + w10*cc.x + w11*dd.x;
            dst[4*q+1] = w00*aa.y + w01*bb.y + w10*cc.y + w11*dd.y;
            dst[4*q+2] = w00*aa.z + w01*bb.z + w10*cc.z + w11*dd.z;
            dst[4*q+3] = w00*aa.w + w01*bb.w + w10*cc.w + w11*dd.w;
        }
        if (sub == 0) {
            float* e = shh + p * SSTR;
            e[0] = cy; e[1] = cx;
            float f = 3.14159265358979323846f;
#pragma unroll
            for (int i = 0; i < NFREQ; i++) {
                float s0, c0, s1, c1;
                sincosf(cy * f, &s0, &c0);
                sincosf(cx * f, &s1, &c1);
                e[2 + 4*i + 0] = s0;   // sin over coord dims
                e[2 + 4*i + 1] = s1;
                e[2 + 4*i + 2] = c0;   // cos over coord dims
                e[2 + 4*i + 3] = c1;
                f *= 2.0f;
            }
        }
    }
    __syncthreads();

    // ---------- 4 FiLM-GELU layers ----------
    mlp_layer<IN0 >(shh, shg, shb, w0, b0, tx, ty);
    mlp_layer<MLPW>(shh, shg, shb, w1, b1, tx, ty);
    mlp_layer<MLPW>(shh, shg, shb, w2, b2, tx, ty);
    mlp_layer<MLPW>(shh, shg, shb, w3, b3, tx, ty);

    // ---------- output head: 256 -> 3, tanh ----------
    if (tid < MTILE * 3) {
        int pp = tid / 3;
        int j  = tid - pp * 3;
        const float* hr = shh + pp * SSTR;
        float acc = __ldg(&bo[j]);
#pragma unroll 8
        for (int k = 0; k < 256; k++)
            acc = fmaf(hr[k], shwo[k * 3 + j], acc);
        out[((size_t)b * NPTS + n0 + pp) * 3 + j] = tanhf(acc);
    }
}

extern "C" void kernel_launch(void* const* d_in, const int* in_sizes, int n_in,
                              void* d_out, int out_size) {
    const float* fgrid  = (const float*)d_in[0];
    const float* ctx    = (const float*)d_in[1];
    const float* coords = (const float*)d_in[2];
    const float* w0 = (const float*)d_in[3];
    const float* b0 = (const float*)d_in[4];
    const float* w1 = (const float*)d_in[5];
    const float* b1 = (const float*)d_in[6];
    const float* w2 = (const float*)d_in[7];
    const float* b2 = (const float*)d_in[8];
    const float* w3 = (const float*)d_in[9];
    const float* b3 = (const float*)d_in[10];
    const float* wf = (const float*)d_in[11];
    const float* bf = (const float*)d_in[12];
    const float* wo = (const float*)d_in[13];
    const float* bo = (const float*)d_in[14];
    float* out = (float*)d_out;

    cudaFuncSetAttribute(decoder_kernel,
                         cudaFuncAttributeMaxDynamicSharedMemorySize, SMEM_BYTES);

    film_kernel<<<BATCH, 2 * MLPW>>>(ctx, wf, bf);
    dim3 grid(NPTS / MTILE, BATCH);
    decoder_kernel<<<grid, 256, SMEM_BYTES>>>(fgrid, coords,
                                              w0, b0, w1, b1, w2, b2, w3, b3,
                                              wo, bo, out);
}

// round 4
// speedup vs baseline: 1.4974x; 1.4943x over previous
#include <cuda_runtime.h>
#include <cuda_bf16.h>
#include <cstdint>
#include <math.h>

#define NPTS   65536
#define BATCH  4
#define DM     128
#define MLPW   256
#define NFREQ  10
#define IN0    170
#define MT     128
#define PI_F   3.14159265358979323846f

// A smem: 128 rows x 264 bf16 (stride 528B)
#define ASTR   528
#define A_HI   0
#define A_LO   67584
// W buffers: 3 x (hi 256x48B + lo 256x48B)
#define WB0    135168
#define WBUF   24576
#define WLO    12288
// params
#define SM_G    208896
#define SM_BETA 209920
#define SM_BIAS 210944
#define SM_WO   215040
#define SMEM_BYTES 218112

__device__ __align__(128) __nv_bfloat16 g_wh[4*256*256];
__device__ __align__(128) __nv_bfloat16 g_wl[4*256*256];
__device__ float g_gamma1[BATCH*MLPW];
__device__ float g_beta[BATCH*MLPW];

__device__ __forceinline__ uint32_t smem_u32(const void* p) {
    uint32_t a;
    asm("{ .reg .u64 t; cvta.to.shared.u64 t, %1; cvt.u32.u64 %0, t; }" : "=r"(a) : "l"(p));
    return a;
}
__device__ __forceinline__ void cp16(uint32_t dst, const void* src) {
    asm volatile("cp.async.cg.shared.global [%0], [%1], 16;" :: "r"(dst), "l"(src));
}
#define CP_COMMIT() asm volatile("cp.async.commit_group;" ::: "memory")
template <int N> __device__ __forceinline__ void cp_wait() {
    asm volatile("cp.async.wait_group %0;" :: "n"(N) : "memory");
}
__device__ __forceinline__ void ldsm4(uint32_t* r, uint32_t addr) {
    asm volatile("ldmatrix.sync.aligned.m8n8.x4.shared.b16 {%0,%1,%2,%3}, [%4];"
                 : "=r"(r[0]), "=r"(r[1]), "=r"(r[2]), "=r"(r[3]) : "r"(addr));
}
__device__ __forceinline__ void mma16816(float* c, const uint32_t* a, const uint32_t* b) {
    asm volatile("mma.sync.aligned.m16n8k16.row.col.f32.bf16.bf16.f32 "
                 "{%0,%1,%2,%3}, {%4,%5,%6,%7}, {%8,%9}, {%0,%1,%2,%3};"
                 : "+f"(c[0]), "+f"(c[1]), "+f"(c[2]), "+f"(c[3])
                 : "r"(a[0]), "r"(a[1]), "r"(a[2]), "r"(a[3]), "r"(b[0]), "r"(b[1]));
}
__device__ __forceinline__ float gelu_fast(float x) {
    float u = 0.7978845608028654f * fmaf(0.044715f * x, x * x, x);
    float e, rc;
    asm("ex2.approx.f32 %0, %1;" : "=f"(e) : "f"(u * 2.8853900817779268f));
    asm("rcp.approx.f32 %0, %1;" : "=f"(rc) : "f"(e + 1.0f));
    return x * (1.0f - rc);
}

// ---------- prep: transpose + bf16 hi/lo split ----------
__global__ void prep_w_kernel(const float* __restrict__ w0, const float* __restrict__ w1,
                              const float* __restrict__ w2, const float* __restrict__ w3) {
    int l = blockIdx.y, k = blockIdx.x, n = threadIdx.x;
    const float* w = (l == 0) ? w0 : (l == 1) ? w1 : (l == 2) ? w2 : w3;
    int kd = (l == 0) ? IN0 : MLPW;
    float v = (k < kd) ? w[k * MLPW + n] : 0.0f;
    __nv_bfloat16 hi = __float2bfloat16_rn(v);
    float lof = v - __bfloat162float(hi);
    g_wh[((size_t)l * 256 + n) * 256 + k] = hi;
    g_wl[((size_t)l * 256 + n) * 256 + k] = __float2bfloat16_rn(lof);
}

__global__ void film_kernel(const float* __restrict__ ctx,
                            const float* __restrict__ wf,
                            const float* __restrict__ bf) {
    int b = blockIdx.x, j = threadIdx.x;
    float acc = bf[j];
    const float* c = ctx + b * DM;
#pragma unroll 4
    for (int k = 0; k < DM; k++)
        acc = fmaf(__ldg(&c[k]), __ldg(&wf[k * 2 * MLPW + j]), acc);
    if (j < MLPW) g_gamma1[b * MLPW + j] = acc + 1.0f;
    else          g_beta[b * MLPW + (j - MLPW)] = acc;
}

// load W chunk (K=16 slice) for (layer l, local chunk c) into buffer buf
__device__ __forceinline__ void load_chunk(uint32_t base, int buf, int l, int c, int tid) {
    uint32_t d = base + WB0 + buf * WBUF + tid * 48;
    const __nv_bfloat16* sh = g_wh + ((size_t)l * 256 + tid) * 256 + c * 16;
    const __nv_bfloat16* sl = g_wl + ((size_t)l * 256 + tid) * 256 + c * 16;
    cp16(d,            sh);
    cp16(d + 16,       sh + 8);
    cp16(d + WLO,      sl);
    cp16(d + WLO + 16, sl + 8);
}

// ---------- main kernel ----------
__global__ void __launch_bounds__(256, 1)
decoder_kernel(const float* __restrict__ fgrid, const float* __restrict__ coords,
               const float* __restrict__ b0p, const float* __restrict__ b1p,
               const float* __restrict__ b2p, const float* __restrict__ b3p,
               const float* __restrict__ wo, const float* __restrict__ bo,
               float* __restrict__ out) {
    extern __shared__ char smc[];
    const uint32_t base = smem_u32(smc);
    const int tid  = threadIdx.x;
    const int w    = tid >> 5, lane = tid & 31;
    const int b    = blockIdx.y;
    const int n0g  = blockIdx.x * MT;
    const int m0   = (w & 1) * 64;           // warp M offset
    const int nw0  = (w >> 1) * 64;          // warp N offset

    // lane-fixed ldmatrix offsets
    const int lg   = lane >> 3, lr = lane & 7;
    const int aRow = lr + ((lg & 1) << 3);          // A row within 16
    const int aKh  = (lg >> 1) << 3;                // A k half
    const int bN   = lr + ((lg >> 1) << 3);         // B n within 16
    const int bKh  = (lg & 1) << 3;                 // B k half
    const uint32_t aOffH = base + A_HI + (uint32_t)(m0 + aRow) * ASTR + aKh * 2;
    const uint32_t aOffL = base + A_LO + (uint32_t)(m0 + aRow) * ASTR + aKh * 2;
    const uint32_t bOff  = (uint32_t)(nw0 + bN) * 48 + bKh * 2;

    // prefetch first two W chunks of layer 0
    load_chunk(base, 0, 0, 0, tid); CP_COMMIT();
    load_chunk(base, 1, 0, 1, tid); CP_COMMIT();

    // stage params
    float* shg   = (float*)(smc + SM_G);
    float* shb   = (float*)(smc + SM_BETA);
    float* sbias = (float*)(smc + SM_BIAS);
    float* swo   = (float*)(smc + SM_WO);
    shg[tid] = g_gamma1[b * MLPW + tid];
    shb[tid] = g_beta[b * MLPW + tid];
    sbias[tid]       = __ldg(&b0p[tid]);
    sbias[256 + tid] = __ldg(&b1p[tid]);
    sbias[512 + tid] = __ldg(&b2p[tid]);
    sbias[768 + tid] = __ldg(&b3p[tid]);
    for (int i = tid; i < 768; i += 256) swo[i] = __ldg(&wo[i]);

    // ---------- phase A: enc + bilinear sample -> A smem (bf16 hi/lo) ----------
    {
        int p = tid >> 1, sub = tid & 1;
        int n = n0g + p;
        float cy = __ldg(&coords[2 * n]), cx = __ldg(&coords[2 * n + 1]);
        float py = fminf(fmaxf((cy + 1.0f) * 31.5f, 0.0f), 63.0f);
        float px = fminf(fmaxf((cx + 1.0f) * 31.5f, 0.0f), 63.0f);
        int y0i = min((int)py, 62), x0i = min((int)px, 62);
        float fy = py - (float)y0i, fx = px - (float)x0i;
        float w00 = (1.f - fy) * (1.f - fx), w01 = (1.f - fy) * fx;
        float w10 = fy * (1.f - fx), w11 = fy * fx;
        const float* gb = fgrid + (((size_t)b * 64 + y0i) * 64 + x0i) * DM;
        char* hb = smc + A_HI + p * ASTR;
        char* lb = smc + A_LO + p * ASTR;
#define PUT(j, v) do { float _v = (v); __nv_bfloat16 _h = __float2bfloat16_rn(_v); \
        *(__nv_bfloat16*)(hb + (j)*2) = _h; \
        *(__nv_bfloat16*)(lb + (j)*2) = __float2bfloat16_rn(_v - __bfloat162float(_h)); } while(0)
        if (sub == 0) {
            PUT(0, cy); PUT(1, cx);
            float sy, cyv, sx, cxv;
            sincosf(PI_F * cy, &sy, &cyv);
            sincosf(PI_F * cx, &sx, &cxv);
#pragma unroll
            for (int i = 0; i < NFREQ; i++) {
                PUT(2 + 4*i + 0, sy);  PUT(2 + 4*i + 1, sx);
                PUT(2 + 4*i + 2, cyv); PUT(2 + 4*i + 3, cxv);
                float ns = 2.f * sy * cyv, nc = 1.f - 2.f * sy * sy;
                sy = ns; cyv = nc;
                ns = 2.f * sx * cxv; nc = 1.f - 2.f * sx * sx;
                sx = ns; cxv = nc;
            }
#pragma unroll 2
            for (int ch = 0; ch < 54; ch++) {
                float v = w00 * __ldg(gb + ch) + w01 * __ldg(gb + DM + ch)
                        + w10 * __ldg(gb + 8192 + ch) + w11 * __ldg(gb + 8192 + DM + ch);
                PUT(42 + ch, v);
            }
        } else {
#pragma unroll 2
            for (int ch = 54; ch < 128; ch++) {
                float v = w00 * __ldg(gb + ch) + w01 * __ldg(gb + DM + ch)
                        + w10 * __ldg(gb + 8192 + ch) + w11 * __ldg(gb + 8192 + DM + ch);
                PUT(42 + ch, v);
            }
#pragma unroll
            for (int j = 170; j < 192; j++) PUT(j, 0.0f);
        }
#undef PUT
    }
    __syncthreads();

    // ---------- mainloop: 60 K=16 chunks over 4 layers ----------
    float acc[4][8][4];
#pragma unroll
    for (int i = 0; i < 4; i++)
#pragma unroll
        for (int j = 0; j < 8; j++)
#pragma unroll
            for (int r = 0; r < 4; r++) acc[i][j][r] = 0.0f;

    int layer = 0, cloc = 0, nch = 12;
#pragma unroll 1
    for (int g = 0; g < 60; g++) {
        cp_wait<1>();
        __syncthreads();
        // prefetch chunk g+2
        {
            int j = g + 2;
            if (j < 60) {
                int ln = (j < 12) ? 0 : (j - 12) / 16 + 1;
                int cn = (ln == 0) ? j : (j - 12) & 15;
                load_chunk(base, j % 3, ln, cn, tid);
            }
            CP_COMMIT();
        }
        // MMAs for chunk g
        {
            const uint32_t wb  = base + WB0 + (uint32_t)(g % 3) * WBUF;
            const uint32_t k2  = (uint32_t)(cloc * 16) * 2;
            uint32_t af[4][4], bfr[4][4];
#pragma unroll
            for (int j2 = 0; j2 < 4; j2++) ldsm4(bfr[j2], wb + bOff + j2 * 768);
#pragma unroll
            for (int i = 0; i < 4; i++) ldsm4(af[i], aOffL + i * (16 * ASTR) + k2);
#pragma unroll
            for (int i = 0; i < 4; i++)
#pragma unroll
                for (int j = 0; j < 8; j++)
                    mma16816(acc[i][j], af[i], &bfr[j >> 1][(j & 1) * 2]);
#pragma unroll
            for (int i = 0; i < 4; i++) ldsm4(af[i], aOffH + i * (16 * ASTR) + k2);
#pragma unroll
            for (int i = 0; i < 4; i++)
#pragma unroll
                for (int j = 0; j < 8; j++)
                    mma16816(acc[i][j], af[i], &bfr[j >> 1][(j & 1) * 2]);
#pragma unroll
            for (int j2 = 0; j2 < 4; j2++) ldsm4(bfr[j2], wb + WLO + bOff + j2 * 768);
#pragma unroll
            for (int i = 0; i < 4; i++)
#pragma unroll
                for (int j = 0; j < 8; j++)
                    mma16816(acc[i][j], af[i], &bfr[j >> 1][(j & 1) * 2]);
        }
        cloc++;
        if (cloc == nch) {
            // ---------- layer epilogue ----------
            __syncthreads();   // all warps done reading A for this layer
            const float* bl = sbias + layer * 256;
            const int cb = nw0 + 2 * (lane & 3);
            const int rb = m0 + (lane >> 2);
#pragma unroll
            for (int j = 0; j < 8; j++) {
                int col = cb + 8 * j;
                float bi0 = bl[col], bi1 = bl[col + 1];
                float gg0 = shg[col], gg1 = shg[col + 1];
                float be0 = shb[col], be1 = shb[col + 1];
#pragma unroll
                for (int i = 0; i < 4; i++) {
                    int row = rb + 16 * i;
                    float z0 = gelu_fast(fmaf(acc[i][j][0] + bi0, gg0, be0));
                    float z1 = gelu_fast(fmaf(acc[i][j][1] + bi1, gg1, be1));
                    float z2 = gelu_fast(fmaf(acc[i][j][2] + bi0, gg0, be0));
                    float z3 = gelu_fast(fmaf(acc[i][j][3] + bi1, gg1, be1));
                    acc[i][j][0] = 0.0f; acc[i][j][1] = 0.0f;
                    acc[i][j][2] = 0.0f; acc[i][j][3] = 0.0f;
                    __nv_bfloat162 h0 = __floats2bfloat162_rn(z0, z1);
                    __nv_bfloat162 l0 = __floats2bfloat162_rn(
                        z0 - __bfloat162float(h0.x), z1 - __bfloat162float(h0.y));
                    __nv_bfloat162 h1 = __floats2bfloat162_rn(z2, z3);
                    __nv_bfloat162 l1 = __floats2bfloat162_rn(
                        z2 - __bfloat162float(h1.x), z3 - __bfloat162float(h1.y));
                    uint32_t o0 = (uint32_t)row * ASTR + (uint32_t)col * 2;
                    uint32_t o1 = o0 + 8 * ASTR;
                    *(uint32_t*)(smc + A_HI + o0) = *(uint32_t*)&h0;
                    *(uint32_t*)(smc + A_LO + o0) = *(uint32_t*)&l0;
                    *(uint32_t*)(smc + A_HI + o1) = *(uint32_t*)&h1;
                    *(uint32_t*)(smc + A_LO + o1) = *(uint32_t*)&l1;
                }
            }
            layer++; cloc = 0; nch = 16;
            // next-iteration __syncthreads orders these writes before ldmatrix reads
        }
    }
    __syncthreads();

    // ---------- head: 256 -> 3, tanh (reconstruct fp32 from hi+lo) ----------
    if (tid < 128) {
        float a0 = __ldg(&bo[0]), a1 = __ldg(&bo[1]), a2 = __ldg(&bo[2]);
        const __nv_bfloat16* hr = (const __nv_bfloat16*)(smc + A_HI + tid * ASTR);
        const __nv_bfloat16* lr = (const __nv_bfloat16*)(smc + A_LO + tid * ASTR);
#pragma unroll 8
        for (int k = 0; k < 256; k++) {
            float hv = __bfloat162float(hr[k]) + __bfloat162float(lr[k]);
            a0 = fmaf(hv, swo[k * 3 + 0], a0);
            a1 = fmaf(hv, swo[k * 3 + 1], a1);
            a2 = fmaf(hv, swo[k * 3 + 2], a2);
        }
        size_t o = ((size_t)b * NPTS + n0g + tid) * 3;
        out[o] = tanhf(a0); out[o + 1] = tanhf(a1); out[o + 2] = tanhf(a2);
    }
}

extern "C" void kernel_launch(void* const* d_in, const int* in_sizes, int n_in,
                              void* d_out, int out_size) {
    const float* fgrid  = (const float*)d_in[0];
    const float* ctx    = (const float*)d_in[1];
    const float* coords = (const float*)d_in[2];
    const float* w0 = (const float*)d_in[3];
    const float* b0 = (const float*)d_in[4];
    const float* w1 = (const float*)d_in[5];
    const float* b1 = (const float*)d_in[6];
    const float* w2 = (const float*)d_in[7];
    const float* b2 = (const float*)d_in[8];
    const float* w3 = (const float*)d_in[9];
    const float* b3 = (const float*)d_in[10];
    const float* wf = (const float*)d_in[11];
    const float* bf = (const float*)d_in[12];
    const float* wo = (const float*)d_in[13];
    const float* bo = (const float*)d_in[14];
    float* out = (float*)d_out;

    cudaFuncSetAttribute(decoder_kernel,
                         cudaFuncAttributeMaxDynamicSharedMemorySize, SMEM_BYTES);

    dim3 pgrid(256, 4);
    prep_w_kernel<<<pgrid, 256>>>(w0, w1, w2, w3);
    film_kernel<<<BATCH, 2 * MLPW>>>(ctx, wf, bf);
    dim3 grid(NPTS / MT, BATCH);
    decoder_kernel<<<grid, 256, SMEM_BYTES>>>(fgrid, coords, b0, b1, b2, b3,
                                              wo, bo, out);
}

// round 6
// speedup vs baseline: 1.8339x; 1.2247x over previous
#include <cuda_runtime.h>
#include <cuda_bf16.h>
#include <cstdint>
#include <math.h>

#define NPTS   65536
#define BATCH  4
#define DM     128
#define MLPW   256
#define NFREQ  10
#define IN0    170
#define MT     128
#define PI_F   3.14159265358979323846f

// A smem: 128 rows x 264 bf16 (stride 528B)
#define ASTR   528
#define A_HI   0
#define A_LO   67584
// W buffers: 3 x (hi 256x48B + lo 256x48B)
#define WB0    135168
#define WBUF   24576
#define WLO    12288
// params
#define SM_G    208896
#define SM_BETA 209920
#define SM_BIAS 210944
#define SM_WO   215040
#define SMEM_BYTES 218112

#define NTHR   512

__device__ __align__(128) __nv_bfloat16 g_wh[4*256*256];
__device__ __align__(128) __nv_bfloat16 g_wl[4*256*256];
__device__ float g_gamma1[BATCH*MLPW];
__device__ float g_beta[BATCH*MLPW];

__device__ __forceinline__ uint32_t smem_u32(const void* p) {
    uint32_t a;
    asm("{ .reg .u64 t; cvta.to.shared.u64 t, %1; cvt.u32.u64 %0, t; }" : "=r"(a) : "l"(p));
    return a;
}
__device__ __forceinline__ void cp16(uint32_t dst, const void* src) {
    asm volatile("cp.async.cg.shared.global [%0], [%1], 16;" :: "r"(dst), "l"(src));
}
#define CP_COMMIT() asm volatile("cp.async.commit_group;" ::: "memory")
template <int N> __device__ __forceinline__ void cp_wait() {
    asm volatile("cp.async.wait_group %0;" :: "n"(N) : "memory");
}
__device__ __forceinline__ void ldsm4(uint32_t* r, uint32_t addr) {
    asm volatile("ldmatrix.sync.aligned.m8n8.x4.shared.b16 {%0,%1,%2,%3}, [%4];"
                 : "=r"(r[0]), "=r"(r[1]), "=r"(r[2]), "=r"(r[3]) : "r"(addr));
}
__device__ __forceinline__ void mma16816(float* c, const uint32_t* a, const uint32_t* b) {
    asm volatile("mma.sync.aligned.m16n8k16.row.col.f32.bf16.bf16.f32 "
                 "{%0,%1,%2,%3}, {%4,%5,%6,%7}, {%8,%9}, {%0,%1,%2,%3};"
                 : "+f"(c[0]), "+f"(c[1]), "+f"(c[2]), "+f"(c[3])
                 : "r"(a[0]), "r"(a[1]), "r"(a[2]), "r"(a[3]), "r"(b[0]), "r"(b[1]));
}
__device__ __forceinline__ float gelu_fast(float x) {
    float u = 0.7978845608028654f * fmaf(0.044715f * x, x * x, x);
    float e, rc;
    asm("ex2.approx.f32 %0, %1;" : "=f"(e) : "f"(u * 2.8853900817779268f));
    asm("rcp.approx.f32 %0, %1;" : "=f"(rc) : "f"(e + 1.0f));
    return x * (1.0f - rc);
}
// truncation hi/lo split of a pair: h = {bf16_trunc(z0), bf16_trunc(z1)}, l = rn(z - h)
__device__ __forceinline__ void split2(float z0, float z1, uint32_t& h, uint32_t& l) {
    uint32_t b0 = __float_as_uint(z0), b1 = __float_as_uint(z1);
    asm("prmt.b32 %0, %1, %2, 0x7632;" : "=r"(h) : "r"(b0), "r"(b1));
    float l0 = z0 - __uint_as_float(b0 & 0xFFFF0000u);
    float l1 = z1 - __uint_as_float(b1 & 0xFFFF0000u);
    __nv_bfloat162 lp = __floats2bfloat162_rn(l0, l1);
    l = *(uint32_t*)&lp;
}

// ---------- prep: transpose + bf16 hi/lo split ----------
__global__ void prep_w_kernel(const float* __restrict__ w0, const float* __restrict__ w1,
                              const float* __restrict__ w2, const float* __restrict__ w3) {
    int l = blockIdx.y, k = blockIdx.x, n = threadIdx.x;
    const float* w = (l == 0) ? w0 : (l == 1) ? w1 : (l == 2) ? w2 : w3;
    int kd = (l == 0) ? IN0 : MLPW;
    float v = (k < kd) ? w[k * MLPW + n] : 0.0f;
    uint32_t bv = __float_as_uint(v);
    // truncation split (keeps hi+lo exact to 2^-16)
    uint16_t hb = (uint16_t)(bv >> 16);
    float lof = v - __uint_as_float(bv & 0xFFFF0000u);
    g_wh[((size_t)l * 256 + n) * 256 + k] = *(__nv_bfloat16*)&hb;
    g_wl[((size_t)l * 256 + n) * 256 + k] = __float2bfloat16_rn(lof);
}

__global__ void film_kernel(const float* __restrict__ ctx,
                            const float* __restrict__ wf,
                            const float* __restrict__ bf) {
    int b = blockIdx.x, j = threadIdx.x;
    float acc = bf[j];
    const float* c = ctx + b * DM;
#pragma unroll 4
    for (int k = 0; k < DM; k++)
        acc = fmaf(__ldg(&c[k]), __ldg(&wf[k * 2 * MLPW + j]), acc);
    if (j < MLPW) g_gamma1[b * MLPW + j] = acc + 1.0f;
    else          g_beta[b * MLPW + (j - MLPW)] = acc;
}

// load W chunk (K=16 slice) for (layer l, local chunk c) into buffer buf (512 thr)
__device__ __forceinline__ void load_chunk(uint32_t base, int buf, int l, int c, int tid) {
    int row  = tid & 255;
    int half = tid >> 8;
    uint32_t d = base + WB0 + buf * WBUF + half * WLO + row * 48;
    const __nv_bfloat16* s = (half ? g_wl : g_wh) + ((size_t)l * 256 + row) * 256 + c * 16;
    cp16(d, s);
    cp16(d + 16, s + 8);
}

// ---------- main kernel ----------
__global__ void __launch_bounds__(NTHR, 1)
decoder_kernel(const float* __restrict__ fgrid, const float* __restrict__ coords,
               const float* __restrict__ b0p, const float* __restrict__ b1p,
               const float* __restrict__ b2p, const float* __restrict__ b3p,
               const float* __restrict__ wo, const float* __restrict__ bo,
               float* __restrict__ out) {
    extern __shared__ char smc[];
    const uint32_t base = smem_u32(smc);
    const int tid  = threadIdx.x;
    const int w    = tid >> 5, lane = tid & 31;
    const int b    = blockIdx.y;
    const int n0g  = blockIdx.x * MT;
    const int m0   = (w & 1) * 64;           // warp M offset
    const int nw0  = (w >> 1) * 32;          // warp N offset (16 warps: 2x8)

    // lane-fixed ldmatrix offsets
    const int lg   = lane >> 3, lr = lane & 7;
    const int aRow = lr + ((lg & 1) << 3);
    const int aKh  = (lg >> 1) << 3;
    const int bN   = lr + ((lg >> 1) << 3);
    const int bKh  = (lg & 1) << 3;
    const uint32_t aOffH = base + A_HI + (uint32_t)(m0 + aRow) * ASTR + aKh * 2;
    const uint32_t aOffL = base + A_LO + (uint32_t)(m0 + aRow) * ASTR + aKh * 2;
    const uint32_t bOff  = (uint32_t)(nw0 + bN) * 48 + bKh * 2;

    // prefetch first two W chunks of layer 0
    load_chunk(base, 0, 0, 0, tid); CP_COMMIT();
    load_chunk(base, 1, 0, 1, tid); CP_COMMIT();

    // stage params
    float* shg   = (float*)(smc + SM_G);
    float* shb   = (float*)(smc + SM_BETA);
    float* sbias = (float*)(smc + SM_BIAS);
    float* swo   = (float*)(smc + SM_WO);
    if (tid < 256) {
        shg[tid] = g_gamma1[b * MLPW + tid];
        shb[tid] = g_beta[b * MLPW + tid];
        sbias[tid]       = __ldg(&b0p[tid]);
        sbias[256 + tid] = __ldg(&b1p[tid]);
        sbias[512 + tid] = __ldg(&b2p[tid]);
        sbias[768 + tid] = __ldg(&b3p[tid]);
    }
    for (int i = tid; i < 768; i += NTHR) swo[i] = __ldg(&wo[i]);

    // ---------- phase A: enc + bilinear sample (vectorized, 4 thr/point) ----------
    {
        int p = tid >> 2, sub = tid & 3;
        int n = n0g + p;
        float cy = __ldg(&coords[2 * n]), cx = __ldg(&coords[2 * n + 1]);
        float py = fminf(fmaxf((cy + 1.0f) * 31.5f, 0.0f), 63.0f);
        float px = fminf(fmaxf((cx + 1.0f) * 31.5f, 0.0f), 63.0f);
        int y0i = min((int)py, 62), x0i = min((int)px, 62);
        float fy = py - (float)y0i, fx = px - (float)x0i;
        float w00 = (1.f - fy) * (1.f - fx), w01 = (1.f - fy) * fx;
        float w10 = fy * (1.f - fx), w11 = fy * fx;
        const float* gb = fgrid + (((size_t)b * 64 + y0i) * 64 + x0i) * DM;
        char* hb = smc + A_HI + p * ASTR;
        char* lb = smc + A_LO + p * ASTR;
#define PUT(j, v) do { float _v = (v); uint32_t _b = __float_as_uint(_v); \
        *(uint16_t*)(hb + 2*(j)) = (uint16_t)(_b >> 16); \
        float _l = _v - __uint_as_float(_b & 0xFFFF0000u); \
        *(__nv_bfloat16*)(lb + 2*(j)) = __float2bfloat16_rn(_l); } while(0)
        // 32 channels per thread, float4 loads from 4 corners
        {
            int cs = sub * 32;
            const float4* q00 = (const float4*)gb + (cs >> 2);
            const float4* q01 = (const float4*)(gb + DM) + (cs >> 2);
            const float4* q10 = (const float4*)(gb + 8192) + (cs >> 2);
            const float4* q11 = (const float4*)(gb + 8192 + DM) + (cs >> 2);
#pragma unroll
            for (int q = 0; q < 8; q++) {
                float4 A = __ldg(q00 + q), B = __ldg(q01 + q);
                float4 C = __ldg(q10 + q), D = __ldg(q11 + q);
                int j0 = 42 + cs + 4 * q;
                PUT(j0 + 0, w00*A.x + w01*B.x + w10*C.x + w11*D.x);
                PUT(j0 + 1, w00*A.y + w01*B.y + w10*C.y + w11*D.y);
                PUT(j0 + 2, w00*A.z + w01*B.z + w10*C.z + w11*D.z);
                PUT(j0 + 3, w00*A.w + w01*B.w + w10*C.w + w11*D.w);
            }
        }
        if (sub == 0) {
            PUT(0, cy); PUT(1, cx);
            float sy, cyv, sx, cxv;
            sincosf(PI_F * cy, &sy, &cyv);
            sincosf(PI_F * cx, &sx, &cxv);
#pragma unroll
            for (int i = 0; i < NFREQ; i++) {
                PUT(2 + 4*i + 0, sy);  PUT(2 + 4*i + 1, sx);
                PUT(2 + 4*i + 2, cyv); PUT(2 + 4*i + 3, cxv);
                float ns = 2.f * sy * cyv, nc = 1.f - 2.f * sy * sy;
                sy = ns; cyv = nc;
                ns = 2.f * sx * cxv; nc = 1.f - 2.f * sx * sx;
                sx = ns; cxv = nc;
            }
        } else if (sub == 3) {
            // zero pad cols 170..191 (bytes 340..384, 4B-aligned)
#pragma unroll
            for (int q = 0; q < 11; q++) {
                *(uint32_t*)(hb + 340 + 4*q) = 0u;
                *(uint32_t*)(lb + 340 + 4*q) = 0u;
            }
        }
#undef PUT
    }
    __syncthreads();

    // ---------- mainloop: 60 K=16 chunks over 4 layers ----------
    float acc[4][4][4];
#pragma unroll
    for (int i = 0; i < 4; i++)
#pragma unroll
        for (int j = 0; j < 4; j++)
#pragma unroll
            for (int r = 0; r < 4; r++) acc[i][j][r] = 0.0f;

    int layer = 0, cloc = 0, nch = 12;
#pragma unroll 1
    for (int g = 0; g < 60; g++) {
        cp_wait<1>();
        __syncthreads();
        // prefetch chunk g+2
        {
            int j = g + 2;
            if (j < 60) {
                int ln = (j < 12) ? 0 : (j - 12) / 16 + 1;
                int cn = (ln == 0) ? j : (j - 12) & 15;
                load_chunk(base, j % 3, ln, cn, tid);
            }
            CP_COMMIT();
        }
        // MMAs for chunk g
        {
            const uint32_t wb = base + WB0 + (uint32_t)(g % 3) * WBUF;
            const uint32_t k2 = (uint32_t)cloc * 32;
            uint32_t af[4][4], bfr[2][4];
#pragma unroll
            for (int j2 = 0; j2 < 2; j2++) ldsm4(bfr[j2], wb + bOff + j2 * 768);
#pragma unroll
            for (int i = 0; i < 4; i++) ldsm4(af[i], aOffL + i * (16 * ASTR) + k2);
#pragma unroll
            for (int i = 0; i < 4; i++)
#pragma unroll
                for (int j = 0; j < 4; j++)
                    mma16816(acc[i][j], af[i], &bfr[j >> 1][(j & 1) * 2]);
#pragma unroll
            for (int i = 0; i < 4; i++) ldsm4(af[i], aOffH + i * (16 * ASTR) + k2);
#pragma unroll
            for (int i = 0; i < 4; i++)
#pragma unroll
                for (int j = 0; j < 4; j++)
                    mma16816(acc[i][j], af[i], &bfr[j >> 1][(j & 1) * 2]);
#pragma unroll
            for (int j2 = 0; j2 < 2; j2++) ldsm4(bfr[j2], wb + WLO + bOff + j2 * 768);
#pragma unroll
            for (int i = 0; i < 4; i++)
#pragma unroll
                for (int j = 0; j < 4; j++)
                    mma16816(acc[i][j], af[i], &bfr[j >> 1][(j & 1) * 2]);
        }
        cloc++;
        if (cloc == nch) {
            // ---------- layer epilogue ----------
            __syncthreads();   // all warps done reading A for this layer
            const float* bl = sbias + layer * 256;
            const int cb = nw0 + 2 * (lane & 3);
            const int rb = m0 + (lane >> 2);
#pragma unroll
            for (int j = 0; j < 4; j++) {
                int col = cb + 8 * j;
                float bi0 = bl[col], bi1 = bl[col + 1];
                float gg0 = shg[col], gg1 = shg[col + 1];
                float be0 = shb[col], be1 = shb[col + 1];
#pragma unroll
                for (int i = 0; i < 4; i++) {
                    int row = rb + 16 * i;
                    float z0 = gelu_fast(fmaf(acc[i][j][0] + bi0, gg0, be0));
                    float z1 = gelu_fast(fmaf(acc[i][j][1] + bi1, gg1, be1));
                    float z2 = gelu_fast(fmaf(acc[i][j][2] + bi0, gg0, be0));
                    float z3 = gelu_fast(fmaf(acc[i][j][3] + bi1, gg1, be1));
                    acc[i][j][0] = 0.0f; acc[i][j][1] = 0.0f;
                    acc[i][j][2] = 0.0f; acc[i][j][3] = 0.0f;
                    uint32_t h0, l0, h1, l1;
                    split2(z0, z1, h0, l0);
                    split2(z2, z3, h1, l1);
                    uint32_t o0 = (uint32_t)row * ASTR + (uint32_t)col * 2;
                    uint32_t o1 = o0 + 8 * ASTR;
                    *(uint32_t*)(smc + A_HI + o0) = h0;
                    *(uint32_t*)(smc + A_LO + o0) = l0;
                    *(uint32_t*)(smc + A_HI + o1) = h1;
                    *(uint32_t*)(smc + A_LO + o1) = l1;
                }
            }
            layer++; cloc = 0; nch = 16;
        }
    }
    __syncthreads();

    // ---------- head: 256 -> 3, tanh (reconstruct fp32 from hi+lo) ----------
    if (tid < 128) {
        float a0 = __ldg(&bo[0]), a1 = __ldg(&bo[1]), a2 = __ldg(&bo[2]);
        const __nv_bfloat16* hr = (const __nv_bfloat16*)(smc + A_HI + tid * ASTR);
        const __nv_bfloat16* lr = (const __nv_bfloat16*)(smc + A_LO + tid * ASTR);
#pragma unroll 8
        for (int k = 0; k < 256; k++) {
            float hv = __bfloat162float(hr[k]) + __bfloat162float(lr[k]);
            a0 = fmaf(hv, swo[k * 3 + 0], a0);
            a1 = fmaf(hv, swo[k * 3 + 1], a1);
            a2 = fmaf(hv, swo[k * 3 + 2], a2);
        }
        size_t o = ((size_t)b * NPTS + n0g + tid) * 3;
        out[o] = tanhf(a0); out[o + 1] = tanhf(a1); out[o + 2] = tanhf(a2);
    }
}

extern "C" void kernel_launch(void* const* d_in, const int* in_sizes, int n_in,
                              void* d_out, int out_size) {
    const float* fgrid  = (const float*)d_in[0];
    const float* ctx    = (const float*)d_in[1];
    const float* coords = (const float*)d_in[2];
    const float* w0 = (const float*)d_in[3];
    const float* b0 = (const float*)d_in[4];
    const float* w1 = (const float*)d_in[5];
    const float* b1 = (const float*)d_in[6];
    const float* w2 = (const float*)d_in[7];
    const float* b2 = (const float*)d_in[8];
    const float* w3 = (const float*)d_in[9];
    const float* b3 = (const float*)d_in[10];
    const float* wf = (const float*)d_in[11];
    const float* bf = (const float*)d_in[12];
    const float* wo = (const float*)d_in[13];
    const float* bo = (const float*)d_in[14];
    float* out = (float*)d_out;

    cudaFuncSetAttribute(decoder_kernel,
                         cudaFuncAttributeMaxDynamicSharedMemorySize, SMEM_BYTES);

    dim3 pgrid(256, 4);
    prep_w_kernel<<<pgrid, 256>>>(w0, w1, w2, w3);
    film_kernel<<<BATCH, 2 * MLPW>>>(ctx, wf, bf);
    dim3 grid(NPTS / MT, BATCH);
    decoder_kernel<<<grid, NTHR, SMEM_BYTES>>>(fgrid, coords, b0, b1, b2, b3,
                                               wo, bo, out);
}

// round 7
// speedup vs baseline: 2.5973x; 1.4162x over previous
#include <cuda_runtime.h>
#include <cuda_fp16.h>
#include <cstdint>
#include <math.h>

#define NPTS   65536
#define BATCH  4
#define DM     128
#define MLPW   256
#define NFREQ  10
#define IN0    170
#define MT     128
#define PI_F   3.14159265358979323846f

// A smem: 128 rows x 264 fp16 (stride 528B), hi + lo planes
#define ASTR   528
#define A_HI   0
#define A_LO   67584
// W buffers: 3 x (256 rows x 48B)  (only hi weights)
#define WB0    135168
#define WBUF   12288
// params
#define SM_G    172032
#define SM_BETA 173056
#define SM_BIAS 174080
#define SM_WO   178176
#define SMEM_BYTES 181248

#define NTHR   512

__device__ __align__(128) __half g_wh[4*256*256];
__device__ float g_gamma1[BATCH*MLPW];
__device__ float g_beta[BATCH*MLPW];

__device__ __forceinline__ uint32_t smem_u32(const void* p) {
    uint32_t a;
    asm("{ .reg .u64 t; cvta.to.shared.u64 t, %1; cvt.u32.u64 %0, t; }" : "=r"(a) : "l"(p));
    return a;
}
__device__ __forceinline__ void cp16(uint32_t dst, const void* src) {
    asm volatile("cp.async.cg.shared.global [%0], [%1], 16;" :: "r"(dst), "l"(src));
}
#define CP_COMMIT() asm volatile("cp.async.commit_group;" ::: "memory")
template <int N> __device__ __forceinline__ void cp_wait() {
    asm volatile("cp.async.wait_group %0;" :: "n"(N) : "memory");
}
__device__ __forceinline__ void ldsm4(uint32_t* r, uint32_t addr) {
    asm volatile("ldmatrix.sync.aligned.m8n8.x4.shared.b16 {%0,%1,%2,%3}, [%4];"
                 : "=r"(r[0]), "=r"(r[1]), "=r"(r[2]), "=r"(r[3]) : "r"(addr));
}
__device__ __forceinline__ void mma16816(float* c, const uint32_t* a, const uint32_t* b) {
    asm volatile("mma.sync.aligned.m16n8k16.row.col.f32.f16.f16.f32 "
                 "{%0,%1,%2,%3}, {%4,%5,%6,%7}, {%8,%9}, {%0,%1,%2,%3};"
                 : "+f"(c[0]), "+f"(c[1]), "+f"(c[2]), "+f"(c[3])
                 : "r"(a[0]), "r"(a[1]), "r"(a[2]), "r"(a[3]), "r"(b[0]), "r"(b[1]));
}
__device__ __forceinline__ float gelu_fast(float x) {
    float u = 0.7978845608028654f * fmaf(0.044715f * x, x * x, x);
    float e, rc;
    asm("ex2.approx.f32 %0, %1;" : "=f"(e) : "f"(u * 2.8853900817779268f));
    asm("rcp.approx.f32 %0, %1;" : "=f"(rc) : "f"(e + 1.0f));
    return x * (1.0f - rc);
}
// fp16 hi/lo split of a pair (rn both stages; a = hi + lo exact to 2^-22)
__device__ __forceinline__ void split2(float z0, float z1, uint32_t& h, uint32_t& l) {
    __half2 hp = __floats2half2_rn(z0, z1);
    h = *(uint32_t*)&hp;
    float r0 = z0 - __half2float(__low2half(hp));
    float r1 = z1 - __half2float(__high2half(hp));
    __half2 lp = __floats2half2_rn(r0, r1);
    l = *(uint32_t*)&lp;
}

// ---------- prep: transpose W, round to fp16 ----------
__global__ void prep_w_kernel(const float* __restrict__ w0, const float* __restrict__ w1,
                              const float* __restrict__ w2, const float* __restrict__ w3) {
    int l = blockIdx.y, k = blockIdx.x, n = threadIdx.x;
    const float* w = (l == 0) ? w0 : (l == 1) ? w1 : (l == 2) ? w2 : w3;
    int kd = (l == 0) ? IN0 : MLPW;
    float v = (k < kd) ? w[k * MLPW + n] : 0.0f;
    g_wh[((size_t)l * 256 + n) * 256 + k] = __float2half_rn(v);
}

__global__ void film_kernel(const float* __restrict__ ctx,
                            const float* __restrict__ wf,
                            const float* __restrict__ bf) {
    int b = blockIdx.x, j = threadIdx.x;
    float acc = bf[j];
    const float* c = ctx + b * DM;
#pragma unroll 4
    for (int k = 0; k < DM; k++)
        acc = fmaf(__ldg(&c[k]), __ldg(&wf[k * 2 * MLPW + j]), acc);
    if (j < MLPW) g_gamma1[b * MLPW + j] = acc + 1.0f;
    else          g_beta[b * MLPW + (j - MLPW)] = acc;
}

// load W chunk (K=16 slice) for (layer l, local chunk c) into buffer buf (512 thr)
__device__ __forceinline__ void load_chunk(uint32_t base, int buf, int l, int c, int tid) {
    int row  = tid >> 1;
    int part = tid & 1;
    uint32_t d = base + WB0 + buf * WBUF + row * 48 + part * 16;
    const __half* s = g_wh + ((size_t)l * 256 + row) * 256 + c * 16 + part * 8;
    cp16(d, s);
}

// ---------- main kernel ----------
__global__ void __launch_bounds__(NTHR, 1)
decoder_kernel(const float* __restrict__ fgrid, const float* __restrict__ coords,
               const float* __restrict__ b0p, const float* __restrict__ b1p,
               const float* __restrict__ b2p, const float* __restrict__ b3p,
               const float* __restrict__ wo, const float* __restrict__ bo,
               float* __restrict__ out) {
    extern __shared__ char smc[];
    const uint32_t base = smem_u32(smc);
    const int tid  = threadIdx.x;
    const int w    = tid >> 5, lane = tid & 31;
    const int b    = blockIdx.y;
    const int n0g  = blockIdx.x * MT;
    const int m0   = (w & 1) * 64;           // warp M offset
    const int nw0  = (w >> 1) * 32;          // warp N offset (16 warps: 2x8)

    // lane-fixed ldmatrix offsets
    const int lg   = lane >> 3, lr = lane & 7;
    const int aRow = lr + ((lg & 1) << 3);
    const int aKh  = (lg >> 1) << 3;
    const int bN   = lr + ((lg >> 1) << 3);
    const int bKh  = (lg & 1) << 3;
    const uint32_t aOffH = base + A_HI + (uint32_t)(m0 + aRow) * ASTR + aKh * 2;
    const uint32_t aOffL = base + A_LO + (uint32_t)(m0 + aRow) * ASTR + aKh * 2;
    const uint32_t bOff  = (uint32_t)(nw0 + bN) * 48 + bKh * 2;

    // prefetch first two W chunks of layer 0
    load_chunk(base, 0, 0, 0, tid); CP_COMMIT();
    load_chunk(base, 1, 0, 1, tid); CP_COMMIT();

    // stage params
    float* shg   = (float*)(smc + SM_G);
    float* shb   = (float*)(smc + SM_BETA);
    float* sbias = (float*)(smc + SM_BIAS);
    float* swo   = (float*)(smc + SM_WO);
    if (tid < 256) {
        shg[tid] = g_gamma1[b * MLPW + tid];
        shb[tid] = g_beta[b * MLPW + tid];
        sbias[tid]       = __ldg(&b0p[tid]);
        sbias[256 + tid] = __ldg(&b1p[tid]);
        sbias[512 + tid] = __ldg(&b2p[tid]);
        sbias[768 + tid] = __ldg(&b3p[tid]);
    }
    for (int i = tid; i < 768; i += NTHR) swo[i] = __ldg(&wo[i]);

    // ---------- phase A: enc + bilinear sample (vectorized, 4 thr/point) ----------
    {
        int p = tid >> 2, sub = tid & 3;
        int n = n0g + p;
        float cy = __ldg(&coords[2 * n]), cx = __ldg(&coords[2 * n + 1]);
        float py = fminf(fmaxf((cy + 1.0f) * 31.5f, 0.0f), 63.0f);
        float px = fminf(fmaxf((cx + 1.0f) * 31.5f, 0.0f), 63.0f);
        int y0i = min((int)py, 62), x0i = min((int)px, 62);
        float fy = py - (float)y0i, fx = px - (float)x0i;
        float w00 = (1.f - fy) * (1.f - fx), w01 = (1.f - fy) * fx;
        float w10 = fy * (1.f - fx), w11 = fy * fx;
        const float* gb = fgrid + (((size_t)b * 64 + y0i) * 64 + x0i) * DM;
        char* hb = smc + A_HI + p * ASTR;
        char* lb = smc + A_LO + p * ASTR;
#define PUT(j, v) do { float _v = (v); __half _h = __float2half_rn(_v); \
        *(__half*)(hb + 2*(j)) = _h; \
        float _l = _v - __half2float(_h); \
        *(__half*)(lb + 2*(j)) = __float2half_rn(_l); } while(0)
        // 32 channels per thread, float4 loads from 4 corners
        {
            int cs = sub * 32;
            const float4* q00 = (const float4*)gb + (cs >> 2);
            const float4* q01 = (const float4*)(gb + DM) + (cs >> 2);
            const float4* q10 = (const float4*)(gb + 8192) + (cs >> 2);
            const float4* q11 = (const float4*)(gb + 8192 + DM) + (cs >> 2);
#pragma unroll
            for (int q = 0; q < 8; q++) {
                float4 A = __ldg(q00 + q), B = __ldg(q01 + q);
                float4 C = __ldg(q10 + q), D = __ldg(q11 + q);
                int j0 = 42 + cs + 4 * q;
                PUT(j0 + 0, w00*A.x + w01*B.x + w10*C.x + w11*D.x);
                PUT(j0 + 1, w00*A.y + w01*B.y + w10*C.y + w11*D.y);
                PUT(j0 + 2, w00*A.z + w01*B.z + w10*C.z + w11*D.z);
                PUT(j0 + 3, w00*A.w + w01*B.w + w10*C.w + w11*D.w);
            }
        }
        if (sub == 0) {
            PUT(0, cy); PUT(1, cx);
            float sy, cyv, sx, cxv;
            sincosf(PI_F * cy, &sy, &cyv);
            sincosf(PI_F * cx, &sx, &cxv);
#pragma unroll
            for (int i = 0; i < NFREQ; i++) {
                PUT(2 + 4*i + 0, sy);  PUT(2 + 4*i + 1, sx);
                PUT(2 + 4*i + 2, cyv); PUT(2 + 4*i + 3, cxv);
                float ns = 2.f * sy * cyv, nc = 1.f - 2.f * sy * sy;
                sy = ns; cyv = nc;
                ns = 2.f * sx * cxv; nc = 1.f - 2.f * sx * sx;
                sx = ns; cxv = nc;
            }
        } else if (sub == 3) {
            // zero pad cols 170..191 (bytes 340..384, 4B-aligned)
#pragma unroll
            for (int q = 0; q < 11; q++) {
                *(uint32_t*)(hb + 340 + 4*q) = 0u;
                *(uint32_t*)(lb + 340 + 4*q) = 0u;
            }
        }
#undef PUT
    }
    __syncthreads();

    // ---------- mainloop: 60 K=16 chunks over 4 layers, 2 passes each ----------
    float acc[4][4][4];
#pragma unroll
    for (int i = 0; i < 4; i++)
#pragma unroll
        for (int j = 0; j < 4; j++)
#pragma unroll
            for (int r = 0; r < 4; r++) acc[i][j][r] = 0.0f;

    int layer = 0, cloc = 0, nch = 12;
#pragma unroll 1
    for (int g = 0; g < 60; g++) {
        cp_wait<1>();
        __syncthreads();
        // prefetch chunk g+2
        {
            int j = g + 2;
            if (j < 60) {
                int ln = (j < 12) ? 0 : (j - 12) / 16 + 1;
                int cn = (ln == 0) ? j : (j - 12) & 15;
                load_chunk(base, j % 3, ln, cn, tid);
            }
            CP_COMMIT();
        }
        // MMAs for chunk g
        {
            const uint32_t wb = base + WB0 + (uint32_t)(g % 3) * WBUF;
            const uint32_t k2 = (uint32_t)cloc * 32;
            uint32_t af[4][4], bfr[2][4];
#pragma unroll
            for (int j2 = 0; j2 < 2; j2++) ldsm4(bfr[j2], wb + bOff + j2 * 768);
            // pass 1: A_hi x W
#pragma unroll
            for (int i = 0; i < 4; i++) ldsm4(af[i], aOffH + i * (16 * ASTR) + k2);
#pragma unroll
            for (int i = 0; i < 4; i++)
#pragma unroll
                for (int j = 0; j < 4; j++)
                    mma16816(acc[i][j], af[i], &bfr[j >> 1][(j & 1) * 2]);
            // pass 2: A_lo x W (reuse af regs)
#pragma unroll
            for (int i = 0; i < 4; i++) ldsm4(af[i], aOffL + i * (16 * ASTR) + k2);
#pragma unroll
            for (int i = 0; i < 4; i++)
#pragma unroll
                for (int j = 0; j < 4; j++)
                    mma16816(acc[i][j], af[i], &bfr[j >> 1][(j & 1) * 2]);
        }
        cloc++;
        if (cloc == nch) {
            // ---------- layer epilogue ----------
            __syncthreads();   // all warps done reading A for this layer
            const float* bl = sbias + layer * 256;
            const int cb = nw0 + 2 * (lane & 3);
            const int rb = m0 + (lane >> 2);
#pragma unroll
            for (int j = 0; j < 4; j++) {
                int col = cb + 8 * j;
                float bi0 = bl[col], bi1 = bl[col + 1];
                float gg0 = shg[col], gg1 = shg[col + 1];
                float be0 = shb[col], be1 = shb[col + 1];
#pragma unroll
                for (int i = 0; i < 4; i++) {
                    int row = rb + 16 * i;
                    float z0 = gelu_fast(fmaf(acc[i][j][0] + bi0, gg0, be0));
                    float z1 = gelu_fast(fmaf(acc[i][j][1] + bi1, gg1, be1));
                    float z2 = gelu_fast(fmaf(acc[i][j][2] + bi0, gg0, be0));
                    float z3 = gelu_fast(fmaf(acc[i][j][3] + bi1, gg1, be1));
                    acc[i][j][0] = 0.0f; acc[i][j][1] = 0.0f;
                    acc[i][j][2] = 0.0f; acc[i][j][3] = 0.0f;
                    uint32_t h0, l0, h1, l1;
                    split2(z0, z1, h0, l0);
                    split2(z2, z3, h1, l1);
                    uint32_t o0 = (uint32_t)row * ASTR + (uint32_t)col * 2;
                    uint32_t o1 = o0 + 8 * ASTR;
                    *(uint32_t*)(smc + A_HI + o0) = h0;
                    *(uint32_t*)(smc + A_LO + o0) = l0;
                    *(uint32_t*)(smc + A_HI + o1) = h1;
                    *(uint32_t*)(smc + A_LO + o1) = l1;
                }
            }
            layer++; cloc = 0; nch = 16;
        }
    }
    __syncthreads();

    // ---------- head: 256 -> 3, tanh (reconstruct fp32 from hi+lo) ----------
    if (tid < 128) {
        float a0 = __ldg(&bo[0]), a1 = __ldg(&bo[1]), a2 = __ldg(&bo[2]);
        const __half* hr = (const __half*)(smc + A_HI + tid * ASTR);
        const __half* lr = (const __half*)(smc + A_LO + tid * ASTR);
#pragma unroll 8
        for (int k = 0; k < 256; k++) {
            float hv = __half2float(hr[k]) + __half2float(lr[k]);
            a0 = fmaf(hv, swo[k * 3 + 0], a0);
            a1 = fmaf(hv, swo[k * 3 + 1], a1);
            a2 = fmaf(hv, swo[k * 3 + 2], a2);
        }
        size_t o = ((size_t)b * NPTS + n0g + tid) * 3;
        out[o] = tanhf(a0); out[o + 1] = tanhf(a1); out[o + 2] = tanhf(a2);
    }
}

extern "C" void kernel_launch(void* const* d_in, const int* in_sizes, int n_in,
                              void* d_out, int out_size) {
    const float* fgrid  = (const float*)d_in[0];
    const float* ctx    = (const float*)d_in[1];
    const float* coords = (const float*)d_in[2];
    const float* w0 = (const float*)d_in[3];
    const float* b0 = (const float*)d_in[4];
    const float* w1 = (const float*)d_in[5];
    const float* b1 = (const float*)d_in[6];
    const float* w2 = (const float*)d_in[7];
    const float* b2 = (const float*)d_in[8];
    const float* w3 = (const float*)d_in[9];
    const float* b3 = (const float*)d_in[10];
    const float* wf = (const float*)d_in[11];
    const float* bf = (const float*)d_in[12];
    const float* wo = (const float*)d_in[13];
    const float* bo = (const float*)d_in[14];
    float* out = (float*)d_out;

    cudaFuncSetAttribute(decoder_kernel,
                         cudaFuncAttributeMaxDynamicSharedMemorySize, SMEM_BYTES);

    dim3 pgrid(256, 4);
    prep_w_kernel<<<pgrid, 256>>>(w0, w1, w2, w3);
    film_kernel<<<BATCH, 2 * MLPW>>>(ctx, wf, bf);
    dim3 grid(NPTS / MT, BATCH);
    decoder_kernel<<<grid, NTHR, SMEM_BYTES>>>(fgrid, coords, b0, b1, b2, b3,
                                               wo, bo, out);
}

// round 8
// speedup vs baseline: 2.6360x; 1.0149x over previous
#include <cuda_runtime.h>
#include <cuda_fp16.h>
#include <cstdint>
#include <math.h>

#define NPTS   65536
#define BATCH  4
#define DM     128
#define MLPW   256
#define NFREQ  10
#define IN0    170
#define MT     128
#define PI_F   3.14159265358979323846f

// A smem: 128 rows x 264 fp16 (stride 528B), hi + lo planes
#define ASTR   528
#define A_HI   0
#define A_LO   67584
// W buffers: 3 x (256 rows x 80B)  (K=32 fp16 = 64B data + 16B pad)
#define WB0    135168
#define WBUF   20480
// params
#define SM_G    196608
#define SM_BETA 197632
#define SM_BIAS 198656
#define SM_WO   202752
#define SMEM_BYTES 205824

#define NTHR   512

__device__ __align__(128) __half g_wh[4*256*256];
__device__ float g_gamma1[BATCH*MLPW];
__device__ float g_beta[BATCH*MLPW];

__device__ __forceinline__ uint32_t smem_u32(const void* p) {
    uint32_t a;
    asm("{ .reg .u64 t; cvta.to.shared.u64 t, %1; cvt.u32.u64 %0, t; }" : "=r"(a) : "l"(p));
    return a;
}
__device__ __forceinline__ void cp16(uint32_t dst, const void* src) {
    asm volatile("cp.async.cg.shared.global [%0], [%1], 16;" :: "r"(dst), "l"(src));
}
#define CP_COMMIT() asm volatile("cp.async.commit_group;" ::: "memory")
template <int N> __device__ __forceinline__ void cp_wait() {
    asm volatile("cp.async.wait_group %0;" :: "n"(N) : "memory");
}
__device__ __forceinline__ void ldsm4(uint32_t* r, uint32_t addr) {
    asm volatile("ldmatrix.sync.aligned.m8n8.x4.shared.b16 {%0,%1,%2,%3}, [%4];"
                 : "=r"(r[0]), "=r"(r[1]), "=r"(r[2]), "=r"(r[3]) : "r"(addr));
}
__device__ __forceinline__ void mma16816(float* c, const uint32_t* a, const uint32_t* b) {
    asm volatile("mma.sync.aligned.m16n8k16.row.col.f32.f16.f16.f32 "
                 "{%0,%1,%2,%3}, {%4,%5,%6,%7}, {%8,%9}, {%0,%1,%2,%3};"
                 : "+f"(c[0]), "+f"(c[1]), "+f"(c[2]), "+f"(c[3])
                 : "r"(a[0]), "r"(a[1]), "r"(a[2]), "r"(a[3]), "r"(b[0]), "r"(b[1]));
}
__device__ __forceinline__ float gelu_fast(float x) {
    float u = 0.7978845608028654f * fmaf(0.044715f * x, x * x, x);
    float e, rc;
    asm("ex2.approx.f32 %0, %1;" : "=f"(e) : "f"(u * 2.8853900817779268f));
    asm("rcp.approx.f32 %0, %1;" : "=f"(rc) : "f"(e + 1.0f));
    return x * (1.0f - rc);
}
// fp16 hi/lo split of a pair (rn both stages; a = hi + lo exact to 2^-22)
__device__ __forceinline__ void split2(float z0, float z1, uint32_t& h, uint32_t& l) {
    __half2 hp = __floats2half2_rn(z0, z1);
    h = *(uint32_t*)&hp;
    float r0 = z0 - __half2float(__low2half(hp));
    float r1 = z1 - __half2float(__high2half(hp));
    __half2 lp = __floats2half2_rn(r0, r1);
    l = *(uint32_t*)&lp;
}

// ---------- prep: transpose W, round to fp16 ----------
__global__ void prep_w_kernel(const float* __restrict__ w0, const float* __restrict__ w1,
                              const float* __restrict__ w2, const float* __restrict__ w3) {
    int l = blockIdx.y, k = blockIdx.x, n = threadIdx.x;
    const float* w = (l == 0) ? w0 : (l == 1) ? w1 : (l == 2) ? w2 : w3;
    int kd = (l == 0) ? IN0 : MLPW;
    float v = (k < kd) ? w[k * MLPW + n] : 0.0f;
    g_wh[((size_t)l * 256 + n) * 256 + k] = __float2half_rn(v);
}

__global__ void film_kernel(const float* __restrict__ ctx,
                            const float* __restrict__ wf,
                            const float* __restrict__ bf) {
    int b = blockIdx.x, j = threadIdx.x;
    float acc = bf[j];
    const float* c = ctx + b * DM;
#pragma unroll 4
    for (int k = 0; k < DM; k++)
        acc = fmaf(__ldg(&c[k]), __ldg(&wf[k * 2 * MLPW + j]), acc);
    if (j < MLPW) g_gamma1[b * MLPW + j] = acc + 1.0f;
    else          g_beta[b * MLPW + (j - MLPW)] = acc;
}

// load W chunk (K=32 slice) for (layer l, local chunk c) into buffer buf (512 thr)
__device__ __forceinline__ void load_chunk(uint32_t base, int buf, int l, int c, int tid) {
    int row  = tid >> 1;
    int part = tid & 1;          // 32B half of the 64B row
    uint32_t d = base + WB0 + buf * WBUF + row * 80 + part * 32;
    const __half* s = g_wh + ((size_t)l * 256 + row) * 256 + c * 32 + part * 16;
    cp16(d, s);
    cp16(d + 16, s + 8);
}

// ---------- main kernel ----------
__global__ void __launch_bounds__(NTHR, 1)
decoder_kernel(const float* __restrict__ fgrid, const float* __restrict__ coords,
               const float* __restrict__ b0p, const float* __restrict__ b1p,
               const float* __restrict__ b2p, const float* __restrict__ b3p,
               const float* __restrict__ wo, const float* __restrict__ bo,
               float* __restrict__ out) {
    extern __shared__ char smc[];
    const uint32_t base = smem_u32(smc);
    const int tid  = threadIdx.x;
    const int w    = tid >> 5, lane = tid & 31;
    const int b    = blockIdx.y;
    const int n0g  = blockIdx.x * MT;
    const int m0   = (w & 1) * 64;           // warp M offset
    const int nw0  = (w >> 1) * 32;          // warp N offset (16 warps: 2x8)

    // lane-fixed ldmatrix offsets
    const int lg   = lane >> 3, lr = lane & 7;
    const int aRow = lr + ((lg & 1) << 3);
    const int aKh  = (lg >> 1) << 3;
    const int bN   = lr + ((lg >> 1) << 3);
    const int bKh  = (lg & 1) << 3;
    const uint32_t aOffH = base + A_HI + (uint32_t)(m0 + aRow) * ASTR + aKh * 2;
    const uint32_t aOffL = base + A_LO + (uint32_t)(m0 + aRow) * ASTR + aKh * 2;
    const uint32_t bOff  = (uint32_t)(nw0 + bN) * 80 + bKh * 2;

    // prefetch first two W chunks of layer 0
    load_chunk(base, 0, 0, 0, tid); CP_COMMIT();
    load_chunk(base, 1, 0, 1, tid); CP_COMMIT();

    // stage params
    float* shg   = (float*)(smc + SM_G);
    float* shb   = (float*)(smc + SM_BETA);
    float* sbias = (float*)(smc + SM_BIAS);
    float* swo   = (float*)(smc + SM_WO);
    if (tid < 256) {
        shg[tid] = g_gamma1[b * MLPW + tid];
        shb[tid] = g_beta[b * MLPW + tid];
        sbias[tid]       = __ldg(&b0p[tid]);
        sbias[256 + tid] = __ldg(&b1p[tid]);
        sbias[512 + tid] = __ldg(&b2p[tid]);
        sbias[768 + tid] = __ldg(&b3p[tid]);
    }
    for (int i = tid; i < 768; i += NTHR) swo[i] = __ldg(&wo[i]);

    // ---------- phase A: enc + bilinear sample (vectorized, 4 thr/point) ----------
    {
        int p = tid >> 2, sub = tid & 3;
        int n = n0g + p;
        float cy = __ldg(&coords[2 * n]), cx = __ldg(&coords[2 * n + 1]);
        float py = fminf(fmaxf((cy + 1.0f) * 31.5f, 0.0f), 63.0f);
        float px = fminf(fmaxf((cx + 1.0f) * 31.5f, 0.0f), 63.0f);
        int y0i = min((int)py, 62), x0i = min((int)px, 62);
        float fy = py - (float)y0i, fx = px - (float)x0i;
        float w00 = (1.f - fy) * (1.f - fx), w01 = (1.f - fy) * fx;
        float w10 = fy * (1.f - fx), w11 = fy * fx;
        const float* gb = fgrid + (((size_t)b * 64 + y0i) * 64 + x0i) * DM;
        char* hb = smc + A_HI + p * ASTR;
        char* lb = smc + A_LO + p * ASTR;
#define PUT(j, v) do { float _v = (v); __half _h = __float2half_rn(_v); \
        *(__half*)(hb + 2*(j)) = _h; \
        float _l = _v - __half2float(_h); \
        *(__half*)(lb + 2*(j)) = __float2half_rn(_l); } while(0)
        // 32 channels per thread, float4 loads from 4 corners
        {
            int cs = sub * 32;
            const float4* q00 = (const float4*)gb + (cs >> 2);
            const float4* q01 = (const float4*)(gb + DM) + (cs >> 2);
            const float4* q10 = (const float4*)(gb + 8192) + (cs >> 2);
            const float4* q11 = (const float4*)(gb + 8192 + DM) + (cs >> 2);
#pragma unroll
            for (int q = 0; q < 8; q++) {
                float4 A = __ldg(q00 + q), B = __ldg(q01 + q);
                float4 C = __ldg(q10 + q), D = __ldg(q11 + q);
                int j0 = 42 + cs + 4 * q;
                PUT(j0 + 0, w00*A.x + w01*B.x + w10*C.x + w11*D.x);
                PUT(j0 + 1, w00*A.y + w01*B.y + w10*C.y + w11*D.y);
                PUT(j0 + 2, w00*A.z + w01*B.z + w10*C.z + w11*D.z);
                PUT(j0 + 3, w00*A.w + w01*B.w + w10*C.w + w11*D.w);
            }
        }
        if (sub == 0) {
            PUT(0, cy); PUT(1, cx);
            float sy, cyv, sx, cxv;
            sincosf(PI_F * cy, &sy, &cyv);
            sincosf(PI_F * cx, &sx, &cxv);
#pragma unroll
            for (int i = 0; i < NFREQ; i++) {
                PUT(2 + 4*i + 0, sy);  PUT(2 + 4*i + 1, sx);
                PUT(2 + 4*i + 2, cyv); PUT(2 + 4*i + 3, cxv);
                float ns = 2.f * sy * cyv, nc = 1.f - 2.f * sy * sy;
                sy = ns; cyv = nc;
                ns = 2.f * sx * cxv; nc = 1.f - 2.f * sx * sx;
                sx = ns; cxv = nc;
            }
        } else if (sub == 3) {
            // zero pad cols 170..191 (bytes 340..384, 4B-aligned)
#pragma unroll
            for (int q = 0; q < 11; q++) {
                *(uint32_t*)(hb + 340 + 4*q) = 0u;
                *(uint32_t*)(lb + 340 + 4*q) = 0u;
            }
        }
#undef PUT
    }
    __syncthreads();

    // ---------- mainloop: 30 K=32 chunks over 4 layers, 2 passes each ----------
    float acc[4][4][4];
#pragma unroll
    for (int i = 0; i < 4; i++)
#pragma unroll
        for (int j = 0; j < 4; j++)
#pragma unroll
            for (int r = 0; r < 4; r++) acc[i][j][r] = 0.0f;

    int layer = 0, cloc = 0, nch = 6;
#pragma unroll 1
    for (int g = 0; g < 30; g++) {
        cp_wait<1>();
        __syncthreads();
        // prefetch chunk g+2
        {
            int j = g + 2;
            if (j < 30) {
                int ln = (j < 6) ? 0 : (j - 6) / 8 + 1;
                int cn = (ln == 0) ? j : (j - 6) & 7;
                load_chunk(base, j % 3, ln, cn, tid);
            }
            CP_COMMIT();
        }
        // MMAs for chunk g (K=32: two k-subtiles of 16)
        {
            const uint32_t wb = base + WB0 + (uint32_t)(g % 3) * WBUF;
            const uint32_t k2 = (uint32_t)cloc * 64;
            uint32_t af[4][4], bfr[2][4];
#pragma unroll
            for (int ks = 0; ks < 2; ks++) {
                const uint32_t kb = k2 + (uint32_t)ks * 32;
#pragma unroll
                for (int j2 = 0; j2 < 2; j2++)
                    ldsm4(bfr[j2], wb + bOff + (uint32_t)ks * 32 + j2 * 1280);
                // pass 1: A_hi x W
#pragma unroll
                for (int i = 0; i < 4; i++) ldsm4(af[i], aOffH + i * (16 * ASTR) + kb);
#pragma unroll
                for (int i = 0; i < 4; i++)
#pragma unroll
                    for (int j = 0; j < 4; j++)
                        mma16816(acc[i][j], af[i], &bfr[j >> 1][(j & 1) * 2]);
                // pass 2: A_lo x W (reuse af regs)
#pragma unroll
                for (int i = 0; i < 4; i++) ldsm4(af[i], aOffL + i * (16 * ASTR) + kb);
#pragma unroll
                for (int i = 0; i < 4; i++)
#pragma unroll
                    for (int j = 0; j < 4; j++)
                        mma16816(acc[i][j], af[i], &bfr[j >> 1][(j & 1) * 2]);
            }
        }
        cloc++;
        if (cloc == nch) {
            // ---------- layer epilogue ----------
            __syncthreads();   // all warps done reading A for this layer
            const float* bl = sbias + layer * 256;
            const int cb = nw0 + 2 * (lane & 3);
            const int rb = m0 + (lane >> 2);
#pragma unroll
            for (int j = 0; j < 4; j++) {
                int col = cb + 8 * j;
                float bi0 = bl[col], bi1 = bl[col + 1];
                float gg0 = shg[col], gg1 = shg[col + 1];
                float be0 = shb[col], be1 = shb[col + 1];
#pragma unroll
                for (int i = 0; i < 4; i++) {
                    int row = rb + 16 * i;
                    float z0 = gelu_fast(fmaf(acc[i][j][0] + bi0, gg0, be0));
                    float z1 = gelu_fast(fmaf(acc[i][j][1] + bi1, gg1, be1));
                    float z2 = gelu_fast(fmaf(acc[i][j][2] + bi0, gg0, be0));
                    float z3 = gelu_fast(fmaf(acc[i][j][3] + bi1, gg1, be1));
                    acc[i][j][0] = 0.0f; acc[i][j][1] = 0.0f;
                    acc[i][j][2] = 0.0f; acc[i][j][3] = 0.0f;
                    uint32_t h0, l0, h1, l1;
                    split2(z0, z1, h0, l0);
                    split2(z2, z3, h1, l1);
                    uint32_t o0 = (uint32_t)row * ASTR + (uint32_t)col * 2;
                    uint32_t o1 = o0 + 8 * ASTR;
                    *(uint32_t*)(smc + A_HI + o0) = h0;
                    *(uint32_t*)(smc + A_LO + o0) = l0;
                    *(uint32_t*)(smc + A_HI + o1) = h1;
                    *(uint32_t*)(smc + A_LO + o1) = l1;
                }
            }
            layer++; cloc = 0; nch = 8;
        }
    }
    __syncthreads();

    // ---------- head: 256 -> 3, tanh (reconstruct fp32 from hi+lo) ----------
    if (tid < 128) {
        float a0 = __ldg(&bo[0]), a1 = __ldg(&bo[1]), a2 = __ldg(&bo[2]);
        const __half* hr = (const __half*)(smc + A_HI + tid * ASTR);
        const __half* lr = (const __half*)(smc + A_LO + tid * ASTR);
#pragma unroll 8
        for (int k = 0; k < 256; k++) {
            float hv = __half2float(hr[k]) + __half2float(lr[k]);
            a0 = fmaf(hv, swo[k * 3 + 0], a0);
            a1 = fmaf(hv, swo[k * 3 + 1], a1);
            a2 = fmaf(hv, swo[k * 3 + 2], a2);
        }
        size_t o = ((size_t)b * NPTS + n0g + tid) * 3;
        out[o] = tanhf(a0); out[o + 1] = tanhf(a1); out[o + 2] = tanhf(a2);
    }
}

extern "C" void kernel_launch(void* const* d_in, const int* in_sizes, int n_in,
                              void* d_out, int out_size) {
    const float* fgrid  = (const float*)d_in[0];
    const float* ctx    = (const float*)d_in[1];
    const float* coords = (const float*)d_in[2];
    const float* w0 = (const float*)d_in[3];
    const float* b0 = (const float*)d_in[4];
    const float* w1 = (const float*)d_in[5];
    const float* b1 = (const float*)d_in[6];
    const float* w2 = (const float*)d_in[7];
    const float* b2 = (const float*)d_in[8];
    const float* w3 = (const float*)d_in[9];
    const float* b3 = (const float*)d_in[10];
    const float* wf = (const float*)d_in[11];
    const float* bf = (const float*)d_in[12];
    const float* wo = (const float*)d_in[13];
    const float* bo = (const float*)d_in[14];
    float* out = (float*)d_out;

    cudaFuncSetAttribute(decoder_kernel,
                         cudaFuncAttributeMaxDynamicSharedMemorySize, SMEM_BYTES);

    dim3 pgrid(256, 4);
    prep_w_kernel<<<pgrid, 256>>>(w0, w1, w2, w3);
    film_kernel<<<BATCH, 2 * MLPW>>>(ctx, wf, bf);
    dim3 grid(NPTS / MT, BATCH);
    decoder_kernel<<<grid, NTHR, SMEM_BYTES>>>(fgrid, coords, b0, b1, b2, b3,
                                               wo, bo, out);
}